// round 1
// baseline (speedup 1.0000x reference)
#include <cuda_runtime.h>
#include <cuda_bf16.h>
#include <math.h>

// Problem constants (fixed by setup_inputs)
#define BB   8
#define LL   273
#define DIM  1536
#define NH   12
#define HD   128
#define ZS   256
#define FH   32
#define MTOT (BB * LL)   // 2184

// ---------------- scratch (no allocations allowed) ----------------
__device__ float g_qbuf[(size_t)MTOT * DIM];
__device__ float g_kbuf[(size_t)MTOT * DIM];
__device__ float g_vbuf[(size_t)MTOT * DIM];
__device__ float g_abuf[(size_t)MTOT * DIM];

// ---------------- tiled fp32 SGEMM: C[m,n] = sum_k A[m,k]*W[n,k] + bias[n] ----
#define BM 128
#define BN 64
#define BK 16
#define TM 8
#define TN 4
// 256 threads: 16x16 thread grid, each thread computes 8x4 outputs.

__global__ __launch_bounds__(256)
void sgemm_bias(const float* __restrict__ A, const float* __restrict__ W,
                const float* __restrict__ bias, float* __restrict__ C, int Mrows)
{
    __shared__ float As[BK][BM + 4];
    __shared__ float Bs[BK][BN + 4];

    const int K = DIM;
    const int bm = blockIdx.y * BM;
    const int bn = blockIdx.x * BN;
    const int tid = threadIdx.x;
    const int tr = tid >> 4;      // 0..15 (row group)
    const int tc = tid & 15;      // 0..15 (col group)

    float acc[TM][TN];
#pragma unroll
    for (int i = 0; i < TM; i++)
#pragma unroll
        for (int j = 0; j < TN; j++) acc[i][j] = 0.f;

    for (int kt = 0; kt < K; kt += BK) {
        // Load A tile: 128 rows x 16 k  = 512 float4, 2 per thread
#pragma unroll
        for (int it = 0; it < 2; it++) {
            int lin = tid + it * 256;          // 0..511
            int row = lin >> 2;                // 4 float4 per row
            int kc  = (lin & 3) << 2;
            int gr  = bm + row;
            float4 v = make_float4(0.f, 0.f, 0.f, 0.f);
            if (gr < Mrows)
                v = *(const float4*)(A + (size_t)gr * K + kt + kc);
            As[kc + 0][row] = v.x; As[kc + 1][row] = v.y;
            As[kc + 2][row] = v.z; As[kc + 3][row] = v.w;
        }
        // Load W tile: 64 rows x 16 k = 256 float4, 1 per thread
        {
            int row = tid >> 2;
            int kc  = (tid & 3) << 2;
            int gn  = bn + row;
            float4 v = *(const float4*)(W + (size_t)gn * K + kt + kc);
            Bs[kc + 0][row] = v.x; Bs[kc + 1][row] = v.y;
            Bs[kc + 2][row] = v.z; Bs[kc + 3][row] = v.w;
        }
        __syncthreads();

#pragma unroll
        for (int kk = 0; kk < BK; kk++) {
            float a[TM], b[TN];
#pragma unroll
            for (int i = 0; i < TM; i++) a[i] = As[kk][tr * TM + i];
#pragma unroll
            for (int j = 0; j < TN; j++) b[j] = Bs[kk][tc * TN + j];
#pragma unroll
            for (int i = 0; i < TM; i++)
#pragma unroll
                for (int j = 0; j < TN; j++)
                    acc[i][j] = fmaf(a[i], b[j], acc[i][j]);
        }
        __syncthreads();
    }

    // store (cols are always in-bounds: 1536 % 64 == 0)
    const int colBase = bn + tc * TN;
    float4 bv = *(const float4*)(bias + colBase);
#pragma unroll
    for (int i = 0; i < TM; i++) {
        int row = bm + tr * TM + i;
        if (row < Mrows) {
            float4 o;
            o.x = acc[i][0] + bv.x;
            o.y = acc[i][1] + bv.y;
            o.z = acc[i][2] + bv.z;
            o.w = acc[i][3] + bv.w;
            *(float4*)(C + (size_t)row * DIM + colBase) = o;
        }
    }
}

// ---------------- rmsnorm over full DIM row (applied to q and k buffers) ----
__global__ __launch_bounds__(256)
void rmsnorm_kernel(const float* __restrict__ gq, const float* __restrict__ gk)
{
    int row = blockIdx.x;            // 0..2*MTOT-1
    float* buf;
    const float* g;
    if (row < MTOT) { buf = g_qbuf + (size_t)row * DIM; g = gq; }
    else            { buf = g_kbuf + (size_t)(row - MTOT) * DIM; g = gk; }

    int tid = threadIdx.x;
    float ss = 0.f;
    for (int i = tid; i < DIM; i += 256) {
        float v = buf[i];
        ss += v * v;
    }
    // block reduce
    __shared__ float sred[8];
    int lane = tid & 31, warp = tid >> 5;
#pragma unroll
    for (int off = 16; off; off >>= 1) ss += __shfl_xor_sync(0xffffffffu, ss, off);
    if (lane == 0) sred[warp] = ss;
    __syncthreads();
    if (warp == 0) {
        float v = (lane < 8) ? sred[lane] : 0.f;
#pragma unroll
        for (int off = 4; off; off >>= 1) v += __shfl_xor_sync(0xffffffffu, v, off);
        if (lane == 0) sred[0] = v;
    }
    __syncthreads();
    float inv = rsqrtf(sred[0] / (float)DIM + 1e-6f);
    for (int i = tid; i < DIM; i += 256)
        buf[i] = buf[i] * inv * g[i];
}

// ---------------- attention: one block per (b, z<ZS, n) ----------------
__global__ __launch_bounds__(128)
void attn_kernel(const float* __restrict__ cache_k, const float* __restrict__ cache_v,
                 const float* __restrict__ rope_table,
                 const int* __restrict__ rridx, const int* __restrict__ cfi_p)
{
    const int bx = blockIdx.x;
    const int n = bx % NH;
    const int z = (bx / NH) % ZS;
    const int b = bx / (NH * ZS);

    const int tid  = threadIdx.x;
    const int lane = tid & 31;
    const int warp = tid >> 5;

    const int cfi   = cfi_p[0];
    const int slot  = cfi % FH;
    const int valid = min(cfi + 1, FH);

    __shared__ float qr[HD];
    __shared__ float prob[FH];

    // rope q with freqs_last = rope_table[cfi, z, :]
    if (tid < HD / 2) {
        int i = tid;
        float f = rope_table[((size_t)cfi * LL + z) * (HD / 2) + i];
        float c = cosf(f), s = sinf(f);
        const float* qp = g_qbuf + (((size_t)(b * LL + z)) * NH + n) * HD;
        float q0 = qp[2 * i], q1 = qp[2 * i + 1];
        qr[2 * i]     = q0 * c - q1 * s;
        qr[2 * i + 1] = q0 * s + q1 * c;
    }
    __syncthreads();

    // scores: warp per frame (strided)
    const float scale = 0.08838834764831845f;  // 1/sqrt(128)
    for (int g = warp; g < valid; g += 4) {
        const float* kp;
        if (g == slot)
            kp = g_kbuf + (((size_t)(b * LL + z)) * NH + n) * HD;
        else
            kp = cache_k + ((((size_t)b * FH + g) * LL + z) * NH + n) * HD;
        int d0 = lane * 4;
        float4 kv = *(const float4*)(kp + d0);
        int ri = rridx[g];
        const float* fp = rope_table + ((size_t)ri * LL + z) * (HD / 2) + (d0 >> 1);
        float f0 = fp[0], f1 = fp[1];
        float c0 = cosf(f0), s0 = sinf(f0);
        float c1 = cosf(f1), s1 = sinf(f1);
        float kr0 = kv.x * c0 - kv.y * s0;
        float kr1 = kv.x * s0 + kv.y * c0;
        float kr2 = kv.z * c1 - kv.w * s1;
        float kr3 = kv.z * s1 + kv.w * c1;
        float p = qr[d0] * kr0 + qr[d0 + 1] * kr1 + qr[d0 + 2] * kr2 + qr[d0 + 3] * kr3;
#pragma unroll
        for (int off = 16; off; off >>= 1) p += __shfl_xor_sync(0xffffffffu, p, off);
        if (lane == 0) prob[g] = p * scale;
    }
    __syncthreads();

    // softmax over g<valid (warp 0)
    if (warp == 0) {
        float v = (lane < valid) ? prob[lane] : -INFINITY;
        float m = v;
#pragma unroll
        for (int off = 16; off; off >>= 1) m = fmaxf(m, __shfl_xor_sync(0xffffffffu, m, off));
        float e = (lane < valid) ? expf(v - m) : 0.f;
        float ssum = e;
#pragma unroll
        for (int off = 16; off; off >>= 1) ssum += __shfl_xor_sync(0xffffffffu, ssum, off);
        if (lane < FH) prob[lane] = e / ssum;
    }
    __syncthreads();

    // output: thread per d
    int d = tid;
    float acc = 0.f;
    for (int g = 0; g < valid; g++) {
        const float* vp;
        if (g == slot)
            vp = g_vbuf + (((size_t)(b * LL + z)) * NH + n) * HD;
        else
            vp = cache_v + ((((size_t)b * FH + g) * LL + z) * NH + n) * HD;
        acc = fmaf(prob[g], vp[d], acc);
    }
    g_abuf[((size_t)(b * LL + z)) * DIM + n * HD + d] = acc;
}

// ---------------- v_cond passthrough for z in [ZS, L) ----------------
__global__ void vcond_kernel()
{
    int idx = blockIdx.x * blockDim.x + threadIdx.x;
    const int total = BB * (LL - ZS) * DIM;
    if (idx >= total) return;
    int c = idx % DIM;
    int t = idx / DIM;
    int z = ZS + (t % (LL - ZS));
    int b = t / (LL - ZS);
    size_t off = ((size_t)(b * LL + z)) * DIM + c;
    g_abuf[off] = g_vbuf[off];
}

// ---------------- launch ----------------
extern "C" void kernel_launch(void* const* d_in, const int* in_sizes, int n_in,
                              void* d_out, int out_size)
{
    const float* x      = (const float*)d_in[0];
    const float* w_q    = (const float*)d_in[1];
    const float* b_q    = (const float*)d_in[2];
    const float* w_k    = (const float*)d_in[3];
    const float* b_k    = (const float*)d_in[4];
    const float* w_v    = (const float*)d_in[5];
    const float* b_v    = (const float*)d_in[6];
    const float* w_o    = (const float*)d_in[7];
    const float* b_o    = (const float*)d_in[8];
    const float* g_q    = (const float*)d_in[9];
    const float* g_k    = (const float*)d_in[10];
    const float* cache_k= (const float*)d_in[11];
    const float* cache_v= (const float*)d_in[12];
    const float* rope_t = (const float*)d_in[13];
    const int*   rridx  = (const int*)d_in[14];
    const int*   cfi    = (const int*)d_in[15];
    float*       out    = (float*)d_out;

    float *qbuf, *kbuf, *vbuf, *abuf;
    cudaGetSymbolAddress((void**)&qbuf, g_qbuf);
    cudaGetSymbolAddress((void**)&kbuf, g_kbuf);
    cudaGetSymbolAddress((void**)&vbuf, g_vbuf);
    cudaGetSymbolAddress((void**)&abuf, g_abuf);

    dim3 ggrid(DIM / BN, (MTOT + BM - 1) / BM);   // (24, 18)

    sgemm_bias<<<ggrid, 256>>>(x, w_q, b_q, qbuf, MTOT);
    sgemm_bias<<<ggrid, 256>>>(x, w_k, b_k, kbuf, MTOT);
    sgemm_bias<<<ggrid, 256>>>(x, w_v, b_v, vbuf, MTOT);

    rmsnorm_kernel<<<2 * MTOT, 256>>>(g_q, g_k);

    attn_kernel<<<BB * ZS * NH, 128>>>(cache_k, cache_v, rope_t, rridx, cfi);

    {
        const int total = BB * (LL - ZS) * DIM;
        vcond_kernel<<<(total + 255) / 256, 256>>>();
    }

    sgemm_bias<<<ggrid, 256>>>(abuf, w_o, b_o, out, MTOT);
}

// round 4
// speedup vs baseline: 2.6576x; 2.6576x over previous
#include <cuda_runtime.h>
#include <cuda_bf16.h>
#include <math.h>

// Problem constants (fixed by setup_inputs)
#define BB   8
#define LL   273
#define DIM  1536
#define NH   12
#define HD   128
#define ZS   256
#define FH   32
#define MTOT (BB * LL)   // 2184

// ---------------- scratch (no allocations allowed) ----------------
__device__ float g_qbuf[(size_t)MTOT * DIM];
__device__ float g_kbuf[(size_t)MTOT * DIM];
__device__ float g_vbuf[(size_t)MTOT * DIM];
__device__ float g_abuf[(size_t)MTOT * DIM];

// ===================== TF32 tensor-core GEMM =====================
// C[m,n] = sum_k A[m,k] * W[n,k] + bias[n]
// Block tile 128x128, BK=32. 8 warps in 2(m) x 4(n); warp tile 64x32.
// mma.sync.aligned.m16n8k8.row.col.f32.tf32.tf32.f32

#define GBM 128
#define GBN 128
#define GBK 32
#define SPAD 36   // padded row length (floats) for As/Bs -> conflict-free

__device__ __forceinline__ unsigned f2tf32(float f) {
    unsigned r;
    asm("cvt.rna.tf32.f32 %0, %1;" : "=r"(r) : "f"(f));
    return r;
}

__device__ __forceinline__ void mma_tf32(float* c, const unsigned* a, const unsigned* b) {
    asm volatile(
        "mma.sync.aligned.m16n8k8.row.col.f32.tf32.tf32.f32 "
        "{%0,%1,%2,%3}, {%4,%5,%6,%7}, {%8,%9}, {%0,%1,%2,%3};"
        : "+f"(c[0]), "+f"(c[1]), "+f"(c[2]), "+f"(c[3])
        : "r"(a[0]), "r"(a[1]), "r"(a[2]), "r"(a[3]),
          "r"(b[0]), "r"(b[1]));
}

// One GEMM body. Works on one (A, W, bias, C) set.
__device__ __forceinline__ void gemm_body(
    const float* __restrict__ A, const float* __restrict__ W,
    const float* __restrict__ bias, float* __restrict__ C, int Mrows,
    float* As /*[128][SPAD]*/, float* Bs /*[128][SPAD]*/)
{
    const int bm = blockIdx.y * GBM;
    const int bn = blockIdx.x * GBN;
    const int tid  = threadIdx.x;
    const int lane = tid & 31;
    const int warp = tid >> 5;
    const int wm = warp >> 2;        // 0..1  -> 64 rows
    const int wn = warp & 3;         // 0..3  -> 32 cols

    float acc[4][4][4];
#pragma unroll
    for (int i = 0; i < 4; i++)
#pragma unroll
        for (int j = 0; j < 4; j++)
#pragma unroll
            for (int r = 0; r < 4; r++) acc[i][j][r] = 0.f;

    const int ldr = tid >> 3;            // 0..31 base row (we load 4 chunks)
    const int ldc = (tid & 7) << 2;      // k-col*4

    for (int kt = 0; kt < DIM; kt += GBK) {
        // ---- load A tile 128x32 (4 float4 per thread) ----
#pragma unroll
        for (int i = 0; i < 4; i++) {
            int row = ldr + i * 32;
            int gr = bm + row;
            float4 v = make_float4(0.f, 0.f, 0.f, 0.f);
            if (gr < Mrows)
                v = *(const float4*)(A + (size_t)gr * DIM + kt + ldc);
            unsigned* dst = (unsigned*)(As + row * SPAD + ldc);
            dst[0] = f2tf32(v.x); dst[1] = f2tf32(v.y);
            dst[2] = f2tf32(v.z); dst[3] = f2tf32(v.w);
        }
        // ---- load W tile 128x32 (always in-bounds: 1536 % 128 == 0) ----
#pragma unroll
        for (int i = 0; i < 4; i++) {
            int row = ldr + i * 32;
            int gn = bn + row;
            float4 v = *(const float4*)(W + (size_t)gn * DIM + kt + ldc);
            unsigned* dst = (unsigned*)(Bs + row * SPAD + ldc);
            dst[0] = f2tf32(v.x); dst[1] = f2tf32(v.y);
            dst[2] = f2tf32(v.z); dst[3] = f2tf32(v.w);
        }
        __syncthreads();

#pragma unroll
        for (int kk = 0; kk < GBK / 8; kk++) {
            unsigned afrag[4][4];
            unsigned bfrag[4][2];
            const int k0 = kk * 8 + (lane & 3);
            const int rsel = lane >> 2;   // 0..7
#pragma unroll
            for (int mt = 0; mt < 4; mt++) {
                const float* ap = As + (wm * 64 + mt * 16 + rsel) * SPAD + k0;
                afrag[mt][0] = *(const unsigned*)(ap);
                afrag[mt][1] = *(const unsigned*)(ap + 8 * SPAD);
                afrag[mt][2] = *(const unsigned*)(ap + 4);
                afrag[mt][3] = *(const unsigned*)(ap + 8 * SPAD + 4);
            }
#pragma unroll
            for (int nt = 0; nt < 4; nt++) {
                const float* bp = Bs + (wn * 32 + nt * 8 + rsel) * SPAD + k0;
                bfrag[nt][0] = *(const unsigned*)(bp);
                bfrag[nt][1] = *(const unsigned*)(bp + 4);
            }
#pragma unroll
            for (int mt = 0; mt < 4; mt++)
#pragma unroll
                for (int nt = 0; nt < 4; nt++)
                    mma_tf32(acc[mt][nt], afrag[mt], bfrag[nt]);
        }
        __syncthreads();
    }

    // ---- epilogue ----
    const int rsel = lane >> 2;
    const int csel = (lane & 3) * 2;
#pragma unroll
    for (int mt = 0; mt < 4; mt++) {
#pragma unroll
        for (int nt = 0; nt < 4; nt++) {
            int col = bn + wn * 32 + nt * 8 + csel;
            float b0 = bias[col], b1 = bias[col + 1];
            int r0 = bm + wm * 64 + mt * 16 + rsel;
            if (r0 < Mrows) {
                float2 o; o.x = acc[mt][nt][0] + b0; o.y = acc[mt][nt][1] + b1;
                *(float2*)(C + (size_t)r0 * DIM + col) = o;
            }
            if (r0 + 8 < Mrows) {
                float2 o; o.x = acc[mt][nt][2] + b0; o.y = acc[mt][nt][3] + b1;
                *(float2*)(C + (size_t)(r0 + 8) * DIM + col) = o;
            }
        }
    }
}

// Fused QKV: blockIdx.z selects which projection
__global__ __launch_bounds__(256)
void gemm_qkv(const float* __restrict__ x,
              const float* __restrict__ w_q, const float* __restrict__ b_q,
              const float* __restrict__ w_k, const float* __restrict__ b_k,
              const float* __restrict__ w_v, const float* __restrict__ b_v)
{
    __shared__ float As[GBM * SPAD];
    __shared__ float Bs[GBN * SPAD];
    const float* W; const float* bias; float* C;
    if (blockIdx.z == 0)      { W = w_q; bias = b_q; C = g_qbuf; }
    else if (blockIdx.z == 1) { W = w_k; bias = b_k; C = g_kbuf; }
    else                      { W = w_v; bias = b_v; C = g_vbuf; }
    gemm_body(x, W, bias, C, MTOT, As, Bs);
}

__global__ __launch_bounds__(256)
void gemm_out(const float* __restrict__ w_o, const float* __restrict__ b_o,
              float* __restrict__ out)
{
    __shared__ float As[GBM * SPAD];
    __shared__ float Bs[GBN * SPAD];
    gemm_body(g_abuf, w_o, b_o, out, MTOT, As, Bs);
}

// ---------------- rmsnorm over full DIM row (applied to q and k buffers) ----
__global__ __launch_bounds__(256)
void rmsnorm_kernel(const float* __restrict__ gq, const float* __restrict__ gk)
{
    int row = blockIdx.x;            // 0..2*MTOT-1
    float* buf;
    const float* g;
    if (row < MTOT) { buf = g_qbuf + (size_t)row * DIM; g = gq; }
    else            { buf = g_kbuf + (size_t)(row - MTOT) * DIM; g = gk; }

    int tid = threadIdx.x;
    float ss = 0.f;
    float vals[6];
#pragma unroll
    for (int i = 0; i < 6; i++) {
        vals[i] = buf[tid + i * 256];
        ss += vals[i] * vals[i];
    }
    __shared__ float sred[8];
    int lane = tid & 31, warp = tid >> 5;
#pragma unroll
    for (int off = 16; off; off >>= 1) ss += __shfl_xor_sync(0xffffffffu, ss, off);
    if (lane == 0) sred[warp] = ss;
    __syncthreads();
    if (warp == 0) {
        float v = (lane < 8) ? sred[lane] : 0.f;
#pragma unroll
        for (int off = 4; off; off >>= 1) v += __shfl_xor_sync(0xffffffffu, v, off);
        if (lane == 0) sred[0] = v;
    }
    __syncthreads();
    float inv = rsqrtf(sred[0] / (float)DIM + 1e-6f);
#pragma unroll
    for (int i = 0; i < 6; i++)
        buf[tid + i * 256] = vals[i] * inv * g[tid + i * 256];
}

// ---------------- attention: one block per (b, z<ZS, n) ----------------
__global__ __launch_bounds__(128)
void attn_kernel(const float* __restrict__ cache_k, const float* __restrict__ cache_v,
                 const float* __restrict__ rope_table,
                 const int* __restrict__ rridx, const int* __restrict__ cfi_p)
{
    const int bx = blockIdx.x;
    const int n = bx % NH;
    const int z = (bx / NH) % ZS;
    const int b = bx / (NH * ZS);

    const int tid  = threadIdx.x;
    const int lane = tid & 31;
    const int warp = tid >> 5;

    const int cfi   = cfi_p[0];
    const int slot  = cfi % FH;
    const int valid = min(cfi + 1, FH);

    __shared__ float qr[HD];
    __shared__ float prob[FH];

    // rope q with freqs_last = rope_table[cfi, z, :]
    if (tid < HD / 2) {
        int i = tid;
        float f = rope_table[((size_t)cfi * LL + z) * (HD / 2) + i];
        float c = cosf(f), s = sinf(f);
        const float* qp = g_qbuf + (((size_t)(b * LL + z)) * NH + n) * HD;
        float q0 = qp[2 * i], q1 = qp[2 * i + 1];
        qr[2 * i]     = q0 * c - q1 * s;
        qr[2 * i + 1] = q0 * s + q1 * c;
    }
    __syncthreads();

    // scores: warp per frame (strided)
    const float scale = 0.08838834764831845f;  // 1/sqrt(128)
    for (int g = warp; g < valid; g += 4) {
        const float* kp;
        if (g == slot)
            kp = g_kbuf + (((size_t)(b * LL + z)) * NH + n) * HD;
        else
            kp = cache_k + ((((size_t)b * FH + g) * LL + z) * NH + n) * HD;
        int d0 = lane * 4;
        float4 kv = *(const float4*)(kp + d0);
        int ri = rridx[g];
        const float* fp = rope_table + ((size_t)ri * LL + z) * (HD / 2) + (d0 >> 1);
        float f0 = fp[0], f1 = fp[1];
        float c0 = cosf(f0), s0 = sinf(f0);
        float c1 = cosf(f1), s1 = sinf(f1);
        float kr0 = kv.x * c0 - kv.y * s0;
        float kr1 = kv.x * s0 + kv.y * c0;
        float kr2 = kv.z * c1 - kv.w * s1;
        float kr3 = kv.z * s1 + kv.w * c1;
        float p = qr[d0] * kr0 + qr[d0 + 1] * kr1 + qr[d0 + 2] * kr2 + qr[d0 + 3] * kr3;
#pragma unroll
        for (int off = 16; off; off >>= 1) p += __shfl_xor_sync(0xffffffffu, p, off);
        if (lane == 0) prob[g] = p * scale;
    }
    __syncthreads();

    // softmax over g<valid (warp 0)
    if (warp == 0) {
        float v = (lane < valid) ? prob[lane] : -INFINITY;
        float m = v;
#pragma unroll
        for (int off = 16; off; off >>= 1) m = fmaxf(m, __shfl_xor_sync(0xffffffffu, m, off));
        float e = (lane < valid) ? expf(v - m) : 0.f;
        float ssum = e;
#pragma unroll
        for (int off = 16; off; off >>= 1) ssum += __shfl_xor_sync(0xffffffffu, ssum, off);
        if (lane < FH) prob[lane] = e / ssum;
    }
    __syncthreads();

    // output: thread per d
    int d = tid;
    float acc = 0.f;
    for (int g = 0; g < valid; g++) {
        const float* vp;
        if (g == slot)
            vp = g_vbuf + (((size_t)(b * LL + z)) * NH + n) * HD;
        else
            vp = cache_v + ((((size_t)b * FH + g) * LL + z) * NH + n) * HD;
        acc = fmaf(prob[g], vp[d], acc);
    }
    g_abuf[((size_t)(b * LL + z)) * DIM + n * HD + d] = acc;
}

// ---------------- v_cond passthrough for z in [ZS, L) ----------------
__global__ void vcond_kernel()
{
    int idx = blockIdx.x * blockDim.x + threadIdx.x;
    const int total = BB * (LL - ZS) * DIM;
    if (idx >= total) return;
    int c = idx % DIM;
    int t = idx / DIM;
    int z = ZS + (t % (LL - ZS));
    int b = t / (LL - ZS);
    size_t off = ((size_t)(b * LL + z)) * DIM + c;
    g_abuf[off] = g_vbuf[off];
}

// ---------------- launch ----------------
extern "C" void kernel_launch(void* const* d_in, const int* in_sizes, int n_in,
                              void* d_out, int out_size)
{
    const float* x      = (const float*)d_in[0];
    const float* w_q    = (const float*)d_in[1];
    const float* b_q    = (const float*)d_in[2];
    const float* w_k    = (const float*)d_in[3];
    const float* b_k    = (const float*)d_in[4];
    const float* w_v    = (const float*)d_in[5];
    const float* b_v    = (const float*)d_in[6];
    const float* w_o    = (const float*)d_in[7];
    const float* b_o    = (const float*)d_in[8];
    const float* g_q    = (const float*)d_in[9];
    const float* g_k    = (const float*)d_in[10];
    const float* cache_k= (const float*)d_in[11];
    const float* cache_v= (const float*)d_in[12];
    const float* rope_t = (const float*)d_in[13];
    const int*   rridx  = (const int*)d_in[14];
    const int*   cfi    = (const int*)d_in[15];
    float*       out    = (float*)d_out;

    dim3 qkvgrid(DIM / GBN, (MTOT + GBM - 1) / GBM, 3);   // (12, 18, 3)
    gemm_qkv<<<qkvgrid, 256>>>(x, w_q, b_q, w_k, b_k, w_v, b_v);

    rmsnorm_kernel<<<2 * MTOT, 256>>>(g_q, g_k);

    attn_kernel<<<BB * ZS * NH, 128>>>(cache_k, cache_v, rope_t, rridx, cfi);

    {
        const int total = BB * (LL - ZS) * DIM;
        vcond_kernel<<<(total + 255) / 256, 256>>>();
    }

    dim3 ogrid(DIM / GBN, (MTOT + GBM - 1) / GBM);        // (12, 18)
    gemm_out<<<ogrid, 256>>>(w_o, b_o, out);
}

// round 6
// speedup vs baseline: 2.6605x; 1.0011x over previous
#include <cuda_runtime.h>
#include <cuda_bf16.h>
#include <cstdint>
#include <cstddef>
#include <math.h>

// Problem constants (fixed by setup_inputs)
#define BB   8
#define LL   273
#define DIM  1536
#define NH   12
#define HD   128
#define ZS   256
#define FH   32
#define MTOT (BB * LL)   // 2184

// ---------------- scratch (no allocations allowed) ----------------
__device__ float g_qbuf[(size_t)MTOT * DIM];
__device__ float g_kbuf[(size_t)MTOT * DIM];
__device__ float g_vbuf[(size_t)MTOT * DIM];
__device__ float g_abuf[(size_t)MTOT * DIM];

// ===================== TF32 tensor-core GEMM (cp.async pipelined) ==========
// C[m,n] = sum_k A[m,k] * W[n,k] + bias[n]
// Block tile 128x128, BK=32, 2-stage cp.async double buffer.
// 8 warps in 2(m) x 4(n); warp tile 64x32.
// mma.sync.aligned.m16n8k8.row.col.f32.tf32.tf32.f32

#define GBM 128
#define GBN 128
#define GBK 32
#define SPAD 36                  // padded row (floats): conflict-free LDS
#define STAGE_F (GBM * SPAD)     // floats per (A or B) stage = 4608
#define SMEM_BYTES (4 * STAGE_F * 4)   // 2 stages x (A+B) = 73728 B

__device__ __forceinline__ unsigned f2tf32(float f) {
    unsigned r;
    asm("cvt.rna.tf32.f32 %0, %1;" : "=r"(r) : "f"(f));
    return r;
}

__device__ __forceinline__ void mma_tf32(float* c, const unsigned* a, const unsigned* b) {
    asm volatile(
        "mma.sync.aligned.m16n8k8.row.col.f32.tf32.tf32.f32 "
        "{%0,%1,%2,%3}, {%4,%5,%6,%7}, {%8,%9}, {%0,%1,%2,%3};"
        : "+f"(c[0]), "+f"(c[1]), "+f"(c[2]), "+f"(c[3])
        : "r"(a[0]), "r"(a[1]), "r"(a[2]), "r"(a[3]),
          "r"(b[0]), "r"(b[1]));
}

__device__ __forceinline__ void cp_async16(unsigned dst, const void* src, int srcbytes) {
    asm volatile("cp.async.cg.shared.global [%0], [%1], 16, %2;"
                 :: "r"(dst), "l"(src), "r"(srcbytes));
}
__device__ __forceinline__ void cp_commit() {
    asm volatile("cp.async.commit_group;");
}
template <int N>
__device__ __forceinline__ void cp_wait() {
    asm volatile("cp.async.wait_group %0;" :: "n"(N));
}

// SPLIT: A row r comes from A2 when (r % LL) >= ZS, else A1.
template <bool SPLIT>
__device__ __forceinline__ void gemm_body(
    const float* __restrict__ A1, const float* __restrict__ A2,
    const float* __restrict__ W,
    const float* __restrict__ bias, float* __restrict__ C, int Mrows)
{
    extern __shared__ float smem_dyn[];
    float* As = smem_dyn;                    // [2][STAGE_F]
    float* Bs = smem_dyn + 2 * STAGE_F;      // [2][STAGE_F]

    const int bm = blockIdx.y * GBM;
    const int bn = blockIdx.x * GBN;
    const int tid  = threadIdx.x;
    const int lane = tid & 31;
    const int warp = tid >> 5;
    const int wm = warp >> 2;        // 0..1  -> 64 rows
    const int wn = warp & 3;         // 0..3  -> 32 cols

    const int ldr = tid >> 3;            // 0..31 base row
    const int ldc = (tid & 7) << 2;      // k offset (floats)

    const unsigned as_base = (unsigned)__cvta_generic_to_shared(As);
    const unsigned bs_base = (unsigned)__cvta_generic_to_shared(Bs);

    // Per-thread source row pointers (A may be split between two buffers)
    const float* aptr[4];
    int abytes[4];
#pragma unroll
    for (int i = 0; i < 4; i++) {
        int row = ldr + i * 32;
        int gr = bm + row;
        int ok = (gr < Mrows);
        int grc = ok ? gr : (Mrows - 1);
        const float* base = A1;
        if (SPLIT && (grc % LL) >= ZS) base = A2;
        aptr[i] = base + (size_t)grc * DIM + ldc;
        abytes[i] = ok ? 16 : 0;
    }
    const float* wptr[4];
#pragma unroll
    for (int i = 0; i < 4; i++) {
        int row = ldr + i * 32;
        wptr[i] = W + (size_t)(bn + row) * DIM + ldc;
    }
    const unsigned adst0 = as_base + (unsigned)(ldr * SPAD + ldc) * 4u;
    const unsigned bdst0 = bs_base + (unsigned)(ldr * SPAD + ldc) * 4u;

    const int NT = DIM / GBK;   // 48

    // ---- prologue: load tile 0 into stage 0 ----
#pragma unroll
    for (int i = 0; i < 4; i++) {
        cp_async16(adst0 + (unsigned)(i * 32 * SPAD) * 4u, aptr[i], abytes[i]);
        cp_async16(bdst0 + (unsigned)(i * 32 * SPAD) * 4u, wptr[i], 16);
    }
    cp_commit();

    float acc[4][4][4];
#pragma unroll
    for (int i = 0; i < 4; i++)
#pragma unroll
        for (int j = 0; j < 4; j++)
#pragma unroll
            for (int r = 0; r < 4; r++) acc[i][j][r] = 0.f;

    const int rsel = lane >> 2;   // 0..7
    const int kbase = lane & 3;   // 0..3

    for (int t = 0; t < NT; t++) {
        const int st = t & 1;
        // issue loads for next tile into other stage
        if (t + 1 < NT) {
            const int sn = (t + 1) & 1;
            const int koff = (t + 1) * GBK;
            const unsigned soff = (unsigned)(sn * STAGE_F) * 4u;
#pragma unroll
            for (int i = 0; i < 4; i++) {
                cp_async16(adst0 + soff + (unsigned)(i * 32 * SPAD) * 4u, aptr[i] + koff, abytes[i]);
                cp_async16(bdst0 + soff + (unsigned)(i * 32 * SPAD) * 4u, wptr[i] + koff, 16);
            }
            cp_commit();
            cp_wait<1>();     // tile t resident
        } else {
            cp_wait<0>();
        }
        __syncthreads();

        const float* as = As + st * STAGE_F;
        const float* bs = Bs + st * STAGE_F;
#pragma unroll
        for (int kk = 0; kk < GBK / 8; kk++) {
            const int k0 = kk * 8 + kbase;
            unsigned afrag[4][4];
            unsigned bfrag[4][2];
#pragma unroll
            for (int mt = 0; mt < 4; mt++) {
                const float* ap = as + (wm * 64 + mt * 16 + rsel) * SPAD + k0;
                afrag[mt][0] = f2tf32(ap[0]);
                afrag[mt][1] = f2tf32(ap[8 * SPAD]);
                afrag[mt][2] = f2tf32(ap[4]);
                afrag[mt][3] = f2tf32(ap[8 * SPAD + 4]);
            }
#pragma unroll
            for (int nt = 0; nt < 4; nt++) {
                const float* bp = bs + (wn * 32 + nt * 8 + rsel) * SPAD + k0;
                bfrag[nt][0] = f2tf32(bp[0]);
                bfrag[nt][1] = f2tf32(bp[4]);
            }
#pragma unroll
            for (int mt = 0; mt < 4; mt++)
#pragma unroll
                for (int nt = 0; nt < 4; nt++)
                    mma_tf32(acc[mt][nt], afrag[mt], bfrag[nt]);
        }
        __syncthreads();
    }

    // ---- epilogue ----
    const int csel = (lane & 3) * 2;
#pragma unroll
    for (int mt = 0; mt < 4; mt++) {
#pragma unroll
        for (int nt = 0; nt < 4; nt++) {
            int col = bn + wn * 32 + nt * 8 + csel;
            float b0 = bias[col], b1 = bias[col + 1];
            int r0 = bm + wm * 64 + mt * 16 + rsel;
            if (r0 < Mrows) {
                float2 o; o.x = acc[mt][nt][0] + b0; o.y = acc[mt][nt][1] + b1;
                *(float2*)(C + (size_t)r0 * DIM + col) = o;
            }
            if (r0 + 8 < Mrows) {
                float2 o; o.x = acc[mt][nt][2] + b0; o.y = acc[mt][nt][3] + b1;
                *(float2*)(C + (size_t)(r0 + 8) * DIM + col) = o;
            }
        }
    }
}

// Fused QKV: blockIdx.z selects which projection
__global__ __launch_bounds__(256)
void gemm_qkv(const float* __restrict__ x,
              const float* __restrict__ w_q, const float* __restrict__ b_q,
              const float* __restrict__ w_k, const float* __restrict__ b_k,
              const float* __restrict__ w_v, const float* __restrict__ b_v)
{
    const float* W; const float* bias; float* C;
    if (blockIdx.z == 0)      { W = w_q; bias = b_q; C = g_qbuf; }
    else if (blockIdx.z == 1) { W = w_k; bias = b_k; C = g_kbuf; }
    else                      { W = w_v; bias = b_v; C = g_vbuf; }
    gemm_body<false>(x, x, W, bias, C, MTOT);
}

// Output projection. A rows: attention out for z<ZS, raw v for z>=ZS.
__global__ __launch_bounds__(256)
void gemm_out(const float* __restrict__ w_o, const float* __restrict__ b_o,
              float* __restrict__ out)
{
    gemm_body<true>(g_abuf, g_vbuf, w_o, b_o, out, MTOT);
}

// ---------------- rmsnorm over full DIM row (applied to q and k buffers) ----
__global__ __launch_bounds__(256)
void rmsnorm_kernel(const float* __restrict__ gq, const float* __restrict__ gk)
{
    int row = blockIdx.x;            // 0..2*MTOT-1
    float* buf;
    const float* g;
    if (row < MTOT) { buf = g_qbuf + (size_t)row * DIM; g = gq; }
    else            { buf = g_kbuf + (size_t)(row - MTOT) * DIM; g = gk; }

    int tid = threadIdx.x;
    float ss = 0.f;
    float vals[6];
#pragma unroll
    for (int i = 0; i < 6; i++) {
        vals[i] = buf[tid + i * 256];
        ss += vals[i] * vals[i];
    }
    __shared__ float sred[8];
    int lane = tid & 31, warp = tid >> 5;
#pragma unroll
    for (int off = 16; off; off >>= 1) ss += __shfl_xor_sync(0xffffffffu, ss, off);
    if (lane == 0) sred[warp] = ss;
    __syncthreads();
    if (warp == 0) {
        float v = (lane < 8) ? sred[lane] : 0.f;
#pragma unroll
        for (int off = 4; off; off >>= 1) v += __shfl_xor_sync(0xffffffffu, v, off);
        if (lane == 0) sred[0] = v;
    }
    __syncthreads();
    float inv = rsqrtf(sred[0] / (float)DIM + 1e-6f);
#pragma unroll
    for (int i = 0; i < 6; i++)
        buf[tid + i * 256] = vals[i] * inv * g[tid + i * 256];
}

// ---------------- attention: one block per (b, z<ZS, n) ----------------
__global__ __launch_bounds__(128)
void attn_kernel(const float* __restrict__ cache_k, const float* __restrict__ cache_v,
                 const float* __restrict__ rope_table,
                 const int* __restrict__ rridx, const int* __restrict__ cfi_p)
{
    const int bx = blockIdx.x;
    const int n = bx % NH;
    const int z = (bx / NH) % ZS;
    const int b = bx / (NH * ZS);

    const int tid  = threadIdx.x;
    const int lane = tid & 31;
    const int warp = tid >> 5;

    const int cfi   = cfi_p[0];
    const int slot  = cfi % FH;
    const int valid = min(cfi + 1, FH);

    __shared__ float qr[HD];
    __shared__ float prob[FH];

    // rope q with freqs_last = rope_table[cfi, z, :]
    if (tid < HD / 2) {
        int i = tid;
        float f = rope_table[((size_t)cfi * LL + z) * (HD / 2) + i];
        float c = cosf(f), s = sinf(f);
        const float* qp = g_qbuf + (((size_t)(b * LL + z)) * NH + n) * HD;
        float q0 = qp[2 * i], q1 = qp[2 * i + 1];
        qr[2 * i]     = q0 * c - q1 * s;
        qr[2 * i + 1] = q0 * s + q1 * c;
    }
    __syncthreads();

    // scores: warp per frame (strided)
    const float scale = 0.08838834764831845f;  // 1/sqrt(128)
    for (int g = warp; g < valid; g += 4) {
        const float* kp;
        if (g == slot)
            kp = g_kbuf + (((size_t)(b * LL + z)) * NH + n) * HD;
        else
            kp = cache_k + ((((size_t)b * FH + g) * LL + z) * NH + n) * HD;
        int d0 = lane * 4;
        float4 kv = *(const float4*)(kp + d0);
        int ri = rridx[g];
        const float* fp = rope_table + ((size_t)ri * LL + z) * (HD / 2) + (d0 >> 1);
        float f0 = fp[0], f1 = fp[1];
        float c0 = cosf(f0), s0 = sinf(f0);
        float c1 = cosf(f1), s1 = sinf(f1);
        float kr0 = kv.x * c0 - kv.y * s0;
        float kr1 = kv.x * s0 + kv.y * c0;
        float kr2 = kv.z * c1 - kv.w * s1;
        float kr3 = kv.z * s1 + kv.w * c1;
        float p = qr[d0] * kr0 + qr[d0 + 1] * kr1 + qr[d0 + 2] * kr2 + qr[d0 + 3] * kr3;
#pragma unroll
        for (int off = 16; off; off >>= 1) p += __shfl_xor_sync(0xffffffffu, p, off);
        if (lane == 0) prob[g] = p * scale;
    }
    __syncthreads();

    // softmax over g<valid (warp 0)
    if (warp == 0) {
        float v = (lane < valid) ? prob[lane] : -INFINITY;
        float m = v;
#pragma unroll
        for (int off = 16; off; off >>= 1) m = fmaxf(m, __shfl_xor_sync(0xffffffffu, m, off));
        float e = (lane < valid) ? expf(v - m) : 0.f;
        float ssum = e;
#pragma unroll
        for (int off = 16; off; off >>= 1) ssum += __shfl_xor_sync(0xffffffffu, ssum, off);
        if (lane < FH) prob[lane] = e / ssum;
    }
    __syncthreads();

    // output: thread per d
    int d = tid;
    float acc = 0.f;
    for (int g = 0; g < valid; g++) {
        const float* vp;
        if (g == slot)
            vp = g_vbuf + (((size_t)(b * LL + z)) * NH + n) * HD;
        else
            vp = cache_v + ((((size_t)b * FH + g) * LL + z) * NH + n) * HD;
        acc = fmaf(prob[g], vp[d], acc);
    }
    g_abuf[((size_t)(b * LL + z)) * DIM + n * HD + d] = acc;
}

// ---------------- launch ----------------
extern "C" void kernel_launch(void* const* d_in, const int* in_sizes, int n_in,
                              void* d_out, int out_size)
{
    const float* x      = (const float*)d_in[0];
    const float* w_q    = (const float*)d_in[1];
    const float* b_q    = (const float*)d_in[2];
    const float* w_k    = (const float*)d_in[3];
    const float* b_k    = (const float*)d_in[4];
    const float* w_v    = (const float*)d_in[5];
    const float* b_v    = (const float*)d_in[6];
    const float* w_o    = (const float*)d_in[7];
    const float* b_o    = (const float*)d_in[8];
    const float* g_q    = (const float*)d_in[9];
    const float* g_k    = (const float*)d_in[10];
    const float* cache_k= (const float*)d_in[11];
    const float* cache_v= (const float*)d_in[12];
    const float* rope_t = (const float*)d_in[13];
    const int*   rridx  = (const int*)d_in[14];
    const int*   cfi    = (const int*)d_in[15];
    float*       out    = (float*)d_out;

    cudaFuncSetAttribute(gemm_qkv, cudaFuncAttributeMaxDynamicSharedMemorySize, SMEM_BYTES);
    cudaFuncSetAttribute(gemm_out, cudaFuncAttributeMaxDynamicSharedMemorySize, SMEM_BYTES);

    dim3 qkvgrid(DIM / GBN, (MTOT + GBM - 1) / GBM, 3);   // (12, 18, 3)
    gemm_qkv<<<qkvgrid, 256, SMEM_BYTES>>>(x, w_q, b_q, w_k, b_k, w_v, b_v);

    rmsnorm_kernel<<<2 * MTOT, 256>>>(g_q, g_k);

    attn_kernel<<<BB * ZS * NH, 128>>>(cache_k, cache_v, rope_t, rridx, cfi);

    dim3 ogrid(DIM / GBN, (MTOT + GBM - 1) / GBM);        // (12, 18)
    gemm_out<<<ogrid, 256, SMEM_BYTES>>>(w_o, b_o, out);
}